// round 5
// baseline (speedup 1.0000x reference)
#include <cuda_runtime.h>
#include <cstdint>
#include <cstddef>

#define THREADS 256
#define NOUT 85

// smem float strides (conflict-free fragment access)
#define SA_STRIDE 136   // A tile rows [32 k][128 m], 128->136
#define SB_STRIDE 36    // B tile rows [96 n][32 k],  32->36
#define SO_STRIDE 132   // out tile [96 n][128 m], 128->132

#define SA_FLOATS (32 * SA_STRIDE)     // 4352
#define SB_FLOATS (96 * SB_STRIDE)     // 3456
#define STAGE_FLOATS (SA_FLOATS + SB_FLOATS)   // 7808 per buffer
#define SMEM_FLOATS_OUT (96 * SO_STRIDE)       // 12672
// two stage buffers (62464 B) >= epilogue (50688 B)
#define DSMEM_BYTES (2 * STAGE_FLOATS * 4)

__device__ __forceinline__ uint32_t f2tf32(float x) {
    uint32_t r; asm("cvt.rna.tf32.f32 %0, %1;" : "=r"(r) : "f"(x)); return r;
}

__device__ __forceinline__ void mma_tf32(float c[4], const uint32_t a[4], const uint32_t b[2]) {
    asm volatile(
        "mma.sync.aligned.m16n8k8.row.col.f32.tf32.tf32.f32 "
        "{%0,%1,%2,%3}, {%4,%5,%6,%7}, {%8,%9}, {%0,%1,%2,%3};"
        : "+f"(c[0]), "+f"(c[1]), "+f"(c[2]), "+f"(c[3])
        : "r"(a[0]), "r"(a[1]), "r"(a[2]), "r"(a[3]), "r"(b[0]), "r"(b[1]));
}

// out[b, o, hw] = sum_c feat[b, c, hw] * W[o, c] + bias[o]
// GEMM: D[m, n], m = flat b*HW+hw (128-tile), n = o (85 -> 96), k = c.
__global__ __launch_bounds__(THREADS, 2)
void head_mma_kernel(const float* __restrict__ f0, const float* __restrict__ f1,
                     const float* __restrict__ f2,
                     const float* __restrict__ w0, const float* __restrict__ w1,
                     const float* __restrict__ w2,
                     const float* __restrict__ bi0, const float* __restrict__ bi1,
                     const float* __restrict__ bi2,
                     float* __restrict__ out)
{
    extern __shared__ float sm[];
    uint32_t* smu = reinterpret_cast<uint32_t*>(sm);

    const int tid  = threadIdx.x;
    const int wid  = tid >> 5;
    const int lane = tid & 31;

    // ---- level dispatch: heavy CTAs first ----
    const float* feat; const float* W; const float* bias; float* ob;
    int C, HW, nch, ntile;
    const int bid = blockIdx.x;
    if (bid < 50)       { feat = f2; W = w2; bias = bi2; ob = out + 10880000; C = 1024; HW = 400;  nch = 32; ntile = bid; }
    else if (bid < 250) { feat = f1; W = w1; bias = bi1; ob = out + 8704000;  C = 512;  HW = 1600; nch = 16; ntile = bid - 50; }
    else                { feat = f0; W = w0; bias = bi0; ob = out;            C = 256;  HW = 6400; nch = 8;  ntile = bid - 250; }

    const int m0 = ntile * 128;

    // ---- staging buffer bases (floats) ----
    const int bufA[2] = { 0, STAGE_FLOATS };
    const int bufB[2] = { SA_FLOATS, STAGE_FLOATS + SA_FLOATS };

    // ---- A staging mapping: 4 float4 per thread per chunk ----
    int aK[4]; size_t aSrcOff[4]; int aDst[4];
#pragma unroll
    for (int i = 0; i < 4; i++) {
        const int idx = tid + 256 * i;
        const int k = idx >> 5;
        const int mq = idx & 31;
        const int p = m0 + mq * 4;         // float4 never crosses batch (HW%4==0)
        const int b = p / HW;
        const int hw = p - b * HW;
        aK[i] = k;
        aSrcOff[i] = (size_t)b * C * HW + hw;
        aDst[i] = k * SA_STRIDE + mq * 4;
    }

    // ---- B staging mapping: 3 float4 per thread per chunk ----
    const int bKq = tid & 7;
    const int bN0 = tid >> 3;

    // ---- warp tile: 4M x 2N grid; warp = 32m x 48n ----
    const int wm = wid & 3;
    const int wn = wid >> 2;
    const int g  = lane >> 2;
    const int tg = lane & 3;
    const int mA = wm * 32 + g;
    const int nB = wn * 48 + g;

    float acc[2][6][4];
#pragma unroll
    for (int i = 0; i < 2; i++)
#pragma unroll
        for (int j = 0; j < 6; j++)
#pragma unroll
            for (int r = 0; r < 4; r++) acc[i][j][r] = 0.f;

    float4 ra[4], rb[3];

    // ---- prologue: chunk 0 -> regs -> buf0; chunk 1 -> regs ----
#pragma unroll
    for (int i = 0; i < 4; i++)
        ra[i] = *reinterpret_cast<const float4*>(feat + aSrcOff[i] + (size_t)aK[i] * HW);
#pragma unroll
    for (int j = 0; j < 3; j++) {
        const int n = bN0 + 32 * j;
        rb[j] = (n < NOUT) ? *reinterpret_cast<const float4*>(W + (size_t)n * C + bKq * 4)
                           : make_float4(0.f, 0.f, 0.f, 0.f);
    }
#pragma unroll
    for (int i = 0; i < 4; i++) {
        uint4 w;
        w.x = f2tf32(ra[i].x); w.y = f2tf32(ra[i].y);
        w.z = f2tf32(ra[i].z); w.w = f2tf32(ra[i].w);
        *reinterpret_cast<uint4*>(&smu[bufA[0] + aDst[i]]) = w;
    }
#pragma unroll
    for (int j = 0; j < 3; j++) {
        uint4 w;
        w.x = f2tf32(rb[j].x); w.y = f2tf32(rb[j].y);
        w.z = f2tf32(rb[j].z); w.w = f2tf32(rb[j].w);
        const int n = bN0 + 32 * j;
        *reinterpret_cast<uint4*>(&smu[bufB[0] + n * SB_STRIDE + bKq * 4]) = w;
    }
    if (nch > 1) {
#pragma unroll
        for (int i = 0; i < 4; i++)
            ra[i] = *reinterpret_cast<const float4*>(feat + aSrcOff[i] + (size_t)(32 + aK[i]) * HW);
#pragma unroll
        for (int j = 0; j < 3; j++) {
            const int n = bN0 + 32 * j;
            rb[j] = (n < NOUT) ? *reinterpret_cast<const float4*>(W + (size_t)n * C + 32 + bKq * 4)
                               : make_float4(0.f, 0.f, 0.f, 0.f);
        }
    }
    __syncthreads();

    // ---- main loop: one sync per chunk ----
    for (int t = 0; t < nch; t++) {
        const int cur = t & 1;
        const int nxt = cur ^ 1;

        // stage chunk t+1 into the other buffer (regs hold it)
        if (t + 1 < nch) {
#pragma unroll
            for (int i = 0; i < 4; i++) {
                uint4 w;
                w.x = f2tf32(ra[i].x); w.y = f2tf32(ra[i].y);
                w.z = f2tf32(ra[i].z); w.w = f2tf32(ra[i].w);
                *reinterpret_cast<uint4*>(&smu[bufA[nxt] + aDst[i]]) = w;
            }
#pragma unroll
            for (int j = 0; j < 3; j++) {
                uint4 w;
                w.x = f2tf32(rb[j].x); w.y = f2tf32(rb[j].y);
                w.z = f2tf32(rb[j].z); w.w = f2tf32(rb[j].w);
                const int n = bN0 + 32 * j;
                *reinterpret_cast<uint4*>(&smu[bufB[nxt] + n * SB_STRIDE + bKq * 4]) = w;
            }
        }
        // prefetch chunk t+2 into regs (lands during MMA below)
        if (t + 2 < nch) {
            const int kc = (t + 2) * 32;
#pragma unroll
            for (int i = 0; i < 4; i++)
                ra[i] = *reinterpret_cast<const float4*>(feat + aSrcOff[i] + (size_t)(kc + aK[i]) * HW);
#pragma unroll
            for (int j = 0; j < 3; j++) {
                const int n = bN0 + 32 * j;
                rb[j] = (n < NOUT) ? *reinterpret_cast<const float4*>(W + (size_t)n * C + kc + bKq * 4)
                                   : make_float4(0.f, 0.f, 0.f, 0.f);
            }
        }

        // compute chunk t from buf[cur]
        const uint32_t* sa = smu + bufA[cur];
        const uint32_t* sb = smu + bufB[cur];
#pragma unroll
        for (int ks = 0; ks < 4; ks++) {
            const int k0 = ks * 8 + tg;
            uint32_t afr[2][4];
#pragma unroll
            for (int i = 0; i < 2; i++) {
                const int mm = mA + 16 * i;
                afr[i][0] = sa[k0 * SA_STRIDE + mm];
                afr[i][1] = sa[k0 * SA_STRIDE + mm + 8];
                afr[i][2] = sa[(k0 + 4) * SA_STRIDE + mm];
                afr[i][3] = sa[(k0 + 4) * SA_STRIDE + mm + 8];
            }
            uint32_t bfr[6][2];
#pragma unroll
            for (int j = 0; j < 6; j++) {
                const int nn = nB + 8 * j;
                bfr[j][0] = sb[nn * SB_STRIDE + k0];
                bfr[j][1] = sb[nn * SB_STRIDE + k0 + 4];
            }
#pragma unroll
            for (int i = 0; i < 2; i++)
#pragma unroll
                for (int j = 0; j < 6; j++)
                    mma_tf32(acc[i][j], afr[i], bfr[j]);
        }

        __syncthreads();
    }

    // ---- epilogue: transpose via smem, coalesced stores ----
    {
        const int mBase = wm * 32 + g;
        const int nBase = wn * 48 + tg * 2;
#pragma unroll
        for (int i = 0; i < 2; i++) {
#pragma unroll
            for (int j = 0; j < 6; j++) {
                const int n = nBase + 8 * j;
                const int m = mBase + 16 * i;
                sm[n * SO_STRIDE + m]           = acc[i][j][0];
                sm[(n + 1) * SO_STRIDE + m]     = acc[i][j][1];
                sm[n * SO_STRIDE + m + 8]       = acc[i][j][2];
                sm[(n + 1) * SO_STRIDE + m + 8] = acc[i][j][3];
            }
        }
    }
    __syncthreads();

#pragma unroll
    for (int j2 = 0; j2 < 12; j2++) {
        const int idx = j2 * 256 + tid;
        const int n = idx >> 5;
        const int mq = idx & 31;
        if (n < NOUT) {
            float4 v = *reinterpret_cast<const float4*>(&sm[n * SO_STRIDE + mq * 4]);
            const float bo = __ldg(&bias[n]);
            v.x += bo; v.y += bo; v.z += bo; v.w += bo;
            const int p = m0 + mq * 4;
            const int b = p / HW;
            const int hw = p - b * HW;
            *reinterpret_cast<float4*>(ob + ((size_t)b * NOUT + n) * HW + hw) = v;
        }
    }
}

extern "C" void kernel_launch(void* const* d_in, const int* in_sizes, int n_in,
                              void* d_out, int out_size)
{
    const float* feat[3] = {nullptr, nullptr, nullptr};
    const float* wgt[3]  = {nullptr, nullptr, nullptr};
    const float* bia[3]  = {nullptr, nullptr, nullptr};
    int bcount = 0;
    for (int i = 0; i < n_in; i++) {
        const int s = in_sizes[i];
        const float* p = (const float*)d_in[i];
        if      (s == 16 * 256 * 6400)  feat[0] = p;
        else if (s == 16 * 512 * 1600)  feat[1] = p;
        else if (s == 16 * 1024 * 400)  feat[2] = p;
        else if (s == 85 * 256)         wgt[0] = p;
        else if (s == 85 * 512)         wgt[1] = p;
        else if (s == 85 * 1024)        wgt[2] = p;
        else if (s == 85 && bcount < 3) bia[bcount++] = p;
    }

    cudaFuncSetAttribute(head_mma_kernel,
                         cudaFuncAttributeMaxDynamicSharedMemorySize, DSMEM_BYTES);

    head_mma_kernel<<<1050, THREADS, DSMEM_BYTES>>>(
        feat[0], feat[1], feat[2],
        wgt[0], wgt[1], wgt[2],
        bia[0], bia[1], bia[2],
        (float*)d_out);
}